// round 2
// baseline (speedup 1.0000x reference)
#include <cuda_runtime.h>
#include <cuda_bf16.h>
#include <math.h>

// Problem constants (fixed by the reference)
#define NN 20000
#define EE 640000
#define GG 128
#define H1 128
#define H2 128
#define RR 8
#define KAGG (RR * GG)   // 1024

// ---------------- scratch (device globals; no allocation allowed) ----------
// NOTE: these are ONLY referenced from device code. Passing a __device__
// symbol as a kernel argument from host code is invalid (that was the R1 bug).
__device__ float g_cnt[NN * RR];           // per (dst, rel) edge counts
__device__ float g_agg[(size_t)NN * KAGG]; // aggregated x per (dst, rel)  ~82MB
__device__ float g_h[NN * H1];             // rgcn output
__device__ float g_q[NN * H2];
__device__ float g_k[NN * H2];
__device__ float g_v[NN * H2];
__device__ float g_score[EE];
__device__ float g_e[EE];
__device__ unsigned g_smaxu[NN];           // monotone-encoded float max
__device__ float g_den[NN];

// pointer codes for the GEMM (resolved in device code)
#define P_AGG 0
#define P_H   1
#define P_EXT 2   // external pointer passed as argument
#define P_Q   3
#define P_K   4
#define P_V   5
#define P_NONE 6

__device__ __forceinline__ const float* resolve_src(int code, const float* ext) {
    switch (code) {
        case P_AGG: return g_agg;
        case P_H:   return g_h;
        case P_EXT: return ext;
        default:    return nullptr;
    }
}
__device__ __forceinline__ float* resolve_dst(int code, float* ext) {
    switch (code) {
        case P_H: return g_h;
        case P_Q: return g_q;
        case P_K: return g_k;
        case P_V: return g_v;
        default:  return ext;
    }
}

// ---------------- zero kernels ---------------------------------------------
__global__ void zero_small_kernel() {
    int i = blockIdx.x * blockDim.x + threadIdx.x;
    if (i < NN * RR) g_cnt[i] = 0.f;
    if (i < NN) { g_smaxu[i] = 0u; g_den[i] = 0.f; }
}

__global__ void zero_agg_kernel() {
    size_t i = ((size_t)blockIdx.x * blockDim.x + threadIdx.x) * 4;
    size_t n = (size_t)NN * KAGG;
    if (i + 3 < n) {
        *(float4*)(&g_agg[i]) = make_float4(0.f, 0.f, 0.f, 0.f);
    } else {
        for (size_t j = i; j < n; j++) g_agg[j] = 0.f;
    }
}

// ---------------- edge counting --------------------------------------------
__global__ void count_kernel(const int* __restrict__ dst,
                             const int* __restrict__ etype) {
    int e = blockIdx.x * blockDim.x + threadIdx.x;
    if (e >= EE) return;
    atomicAdd(&g_cnt[dst[e] * RR + etype[e]], 1.0f);
}

// ---------------- RGCN scatter: agg[dst, rel] += x[src]/cnt ----------------
__global__ void scatter_rgcn_kernel(const int* __restrict__ src,
                                    const int* __restrict__ dst,
                                    const int* __restrict__ etype,
                                    const float* __restrict__ x) {
    int e = blockIdx.x * 8 + (threadIdx.x >> 5);
    if (e >= EE) return;
    int lane = threadIdx.x & 31;
    int s = src[e], d = dst[e], r = etype[e];
    float denom = fmaxf(g_cnt[d * RR + r], 1.0f);
    float inv = 1.0f / denom;
    const float* xs = x + (size_t)s * GG;
    float* ag = g_agg + (size_t)d * KAGG + r * GG;
    #pragma unroll
    for (int i = lane; i < GG; i += 32)
        atomicAdd(&ag[i], xs[i] * inv);
}

// ---------------- tiled GEMM: C[M,128] = A1@B1 (+A2@B2) + bias (+relu) -----
// B matrices are [K,128] row-major (ldb=128). BM=64, BN=128, BK=16.
__global__ void gemm_kernel(int a1_code, int lda1, int K1,
                            const float* __restrict__ B1,
                            int a2_code, const float* __restrict__ a2_ext,
                            int lda2, int K2,
                            const float* __restrict__ B2,
                            const float* __restrict__ bias,
                            int c_code, float* __restrict__ c_ext,
                            int M, int do_relu) {
    __shared__ float As[16][64];
    __shared__ float Bs[16][128];
    int tid = threadIdx.x;
    int tx = tid & 15;   // col group: cols tx + 16*j
    int ty = tid >> 4;   // row group: rows ty + 16*i
    int row0 = blockIdx.x * 64;

    float acc[4][8];
    #pragma unroll
    for (int i = 0; i < 4; i++)
        #pragma unroll
        for (int j = 0; j < 8; j++) acc[i][j] = 0.f;

    for (int seg = 0; seg < 2; seg++) {
        const float* A = seg ? resolve_src(a2_code, a2_ext)
                             : resolve_src(a1_code, a2_ext);
        const float* B = seg ? B2 : B1;
        int K = seg ? K2 : K1;
        int lda = seg ? lda2 : lda1;
        if (A == nullptr || B == nullptr || K == 0) continue;
        for (int k0 = 0; k0 < K; k0 += 16) {
            #pragma unroll
            for (int i = 0; i < 4; i++) {
                int idx = tid + i * 256;
                int r = idx >> 4, kk = idx & 15;
                int gr = row0 + r;
                As[kk][r] = (gr < M) ? A[(size_t)gr * lda + k0 + kk] : 0.f;
            }
            #pragma unroll
            for (int i = 0; i < 8; i++) {
                int idx = tid + i * 256;
                int kk = idx >> 7, c = idx & 127;
                Bs[kk][c] = B[(size_t)(k0 + kk) * 128 + c];
            }
            __syncthreads();
            #pragma unroll
            for (int kk = 0; kk < 16; kk++) {
                float a[4], b[8];
                #pragma unroll
                for (int i = 0; i < 4; i++) a[i] = As[kk][ty + 16 * i];
                #pragma unroll
                for (int j = 0; j < 8; j++) b[j] = Bs[kk][tx + 16 * j];
                #pragma unroll
                for (int i = 0; i < 4; i++)
                    #pragma unroll
                    for (int j = 0; j < 8; j++) acc[i][j] += a[i] * b[j];
            }
            __syncthreads();
        }
    }

    float* C = resolve_dst(c_code, c_ext);
    #pragma unroll
    for (int i = 0; i < 4; i++) {
        int r = row0 + ty + 16 * i;
        if (r >= M) continue;
        #pragma unroll
        for (int j = 0; j < 8; j++) {
            int c = tx + 16 * j;
            float vv = acc[i][j] + bias[c];
            if (do_relu) vv = fmaxf(vv, 0.f);
            C[(size_t)r * 128 + c] = vv;
        }
    }
}

// ---------------- attention score + segment max ----------------------------
__device__ __forceinline__ unsigned enc_f(float f) {
    unsigned b = __float_as_uint(f);
    return (b & 0x80000000u) ? ~b : (b | 0x80000000u);
}
__device__ __forceinline__ float dec_u(unsigned u) {
    unsigned b = (u & 0x80000000u) ? (u & 0x7FFFFFFFu) : ~u;
    return __uint_as_float(b);
}

__global__ void score_kernel(const int* __restrict__ src,
                             const int* __restrict__ dst) {
    int e = blockIdx.x * 8 + (threadIdx.x >> 5);
    if (e >= EE) return;
    int lane = threadIdx.x & 31;
    int s = src[e], d = dst[e];
    const float* qd = g_q + (size_t)d * H2;
    const float* ks = g_k + (size_t)s * H2;
    float acc = 0.f;
    #pragma unroll
    for (int i = lane; i < H2; i += 32) acc += qd[i] * ks[i];
    #pragma unroll
    for (int o = 16; o; o >>= 1) acc += __shfl_xor_sync(0xFFFFFFFFu, acc, o);
    if (lane == 0) {
        float sc = acc * 0.08838834764831845f;  // 1/sqrt(128)
        g_score[e] = sc;
        atomicMax(&g_smaxu[d], enc_f(sc));
    }
}

// ---------------- softmax numerator + denominator --------------------------
__global__ void exp_kernel(const int* __restrict__ dst) {
    int e = blockIdx.x * blockDim.x + threadIdx.x;
    if (e >= EE) return;
    int d = dst[e];
    float m = dec_u(g_smaxu[d]);
    float ex = expf(g_score[e] - m);
    g_e[e] = ex;
    atomicAdd(&g_den[d], ex);
}

// ---------------- weighted V scatter ---------------------------------------
__global__ void scatter_v_kernel(const int* __restrict__ src,
                                 const int* __restrict__ dst,
                                 float* __restrict__ out) {
    int e = blockIdx.x * 8 + (threadIdx.x >> 5);
    if (e >= EE) return;
    int lane = threadIdx.x & 31;
    int s = src[e], d = dst[e];
    float alpha = g_e[e] / fmaxf(g_den[d], 1e-16f);
    const float* vs = g_v + (size_t)s * H2;
    float* od = out + (size_t)d * H2;
    #pragma unroll
    for (int i = lane; i < H2; i += 32)
        atomicAdd(&od[i], alpha * vs[i]);
}

// ---------------- final relu in place --------------------------------------
__global__ void relu_kernel(float* __restrict__ out, int n) {
    int i = blockIdx.x * blockDim.x + threadIdx.x;
    if (i < n) out[i] = fmaxf(out[i], 0.f);
}

// ---------------------------------------------------------------------------
extern "C" void kernel_launch(void* const* d_in, const int* in_sizes, int n_in,
                              void* d_out, int out_size) {
    const float* x        = (const float*)d_in[0];
    const int* edge_index = (const int*)d_in[1];   // [2, E]: src then dst
    const int* etype      = (const int*)d_in[2];
    const float* rgcn_w   = (const float*)d_in[3]; // [R, G, H1] == [1024,128]
    const float* rgcn_root= (const float*)d_in[4]; // [G, H1]
    const float* rgcn_b   = (const float*)d_in[5];
    const float* Wq = (const float*)d_in[6];  const float* bq = (const float*)d_in[7];
    const float* Wk = (const float*)d_in[8];  const float* bk = (const float*)d_in[9];
    const float* Wv = (const float*)d_in[10]; const float* bv = (const float*)d_in[11];
    const float* Ws = (const float*)d_in[12]; const float* bs = (const float*)d_in[13];
    float* out = (float*)d_out;

    const int* src = edge_index;
    const int* dst = edge_index + EE;

    // 1. zero scratch
    zero_small_kernel<<<(NN * RR + 255) / 256, 256>>>();
    {
        size_t n4 = ((size_t)NN * KAGG + 3) / 4;
        zero_agg_kernel<<<(int)((n4 + 255) / 256), 256>>>();
    }

    // 2. per-(dst,rel) counts
    count_kernel<<<(EE + 255) / 256, 256>>>(dst, etype);

    // 3. RGCN aggregation (warp per edge, 8 warps/block)
    scatter_rgcn_kernel<<<(EE + 7) / 8, 256>>>(src, dst, etype, x);

    // 4. h = relu(agg @ W_stack + x @ root + bias)
    int gm = (NN + 63) / 64;
    gemm_kernel<<<gm, 256>>>(P_AGG, KAGG, KAGG, rgcn_w,
                             P_EXT, x, GG, GG, rgcn_root,
                             rgcn_b, P_H, nullptr, NN, 1);

    // 5. q, k, v, skip(->d_out)
    gemm_kernel<<<gm, 256>>>(P_H, H1, H1, Wq, P_NONE, nullptr, 0, 0, nullptr,
                             bq, P_Q, nullptr, NN, 0);
    gemm_kernel<<<gm, 256>>>(P_H, H1, H1, Wk, P_NONE, nullptr, 0, 0, nullptr,
                             bk, P_K, nullptr, NN, 0);
    gemm_kernel<<<gm, 256>>>(P_H, H1, H1, Wv, P_NONE, nullptr, 0, 0, nullptr,
                             bv, P_V, nullptr, NN, 0);
    gemm_kernel<<<gm, 256>>>(P_H, H1, H1, Ws, P_NONE, nullptr, 0, 0, nullptr,
                             bs, P_EXT, out, NN, 0);

    // 6. attention scores + segment max
    score_kernel<<<(EE + 7) / 8, 256>>>(src, dst);

    // 7. exp + denominator
    exp_kernel<<<(EE + 255) / 256, 256>>>(dst);

    // 8. alpha * v scatter into out (on top of skip)
    scatter_v_kernel<<<(EE + 7) / 8, 256>>>(src, dst, out);

    // 9. final relu
    relu_kernel<<<(NN * H2 + 255) / 256, 256>>>(out, NN * H2);
}